// round 5
// baseline (speedup 1.0000x reference)
#include <cuda_runtime.h>
#include <cstdint>

// COEFFS table from the reference: 9 programs x 4 coeffs (h1, h2, r1, r2)
__constant__ float COEF[9][4] = {
    { 1.f,  0.f,  0.f,  0.f},
    { 0.f,  0.f,  1.f,  0.f},
    { 1.f,  0.f,  1.f,  0.f},
    { 1.f,  1.f,  0.f,  0.f},
    { 0.f,  0.f,  1.f,  1.f},
    { 1.f, -1.f,  0.f,  0.f},
    { 1.f,  0.f, -1.f,  0.f},
    {-1.f,  0.f,  1.f,  0.f},
    { 0.f,  0.f,  1.f, -1.f},
};

// One block per (b, s) image pair. Each pair owns:
//   hearts: 2 planes of 64*64 = 4096 f32 (h1 then h2, contiguous)
//   rects : 2 planes of 4096 f32 (r1 then r2)
//   out   : 1 plane of 4096 f32
// 4096 f32 = 1024 float4 per plane. 256 threads x 4 float4 each.
// The coeff-driven branches are uniform across the whole block (same
// program_id), so skipped planes are never loaded — avg 1.89/4 planes read.

__global__ __launch_bounds__(256, 8)
void tgm_kernel(const int* __restrict__ pid,
                const float* __restrict__ hearts,
                const float* __restrict__ rects,
                float* __restrict__ out)
{
    const int pair = blockIdx.x;            // 0..8191
    const int p    = pid[pair];             // 0..8

    const float c0 = COEF[p][0];
    const float c1 = COEF[p][1];
    const float c2 = COEF[p][2];
    const float c3 = COEF[p][3];

    const size_t in_base  = (size_t)pair * 8192;  // 2 planes per tensor
    const size_t out_base = (size_t)pair * 4096;

    const float4* __restrict__ h1 = (const float4*)(hearts + in_base);
    const float4* __restrict__ h2 = h1 + 1024;
    const float4* __restrict__ r1 = (const float4*)(rects + in_base);
    const float4* __restrict__ r2 = r1 + 1024;
    float4*       __restrict__ o  = (float4*)(out + out_base);

    const int tid = threadIdx.x;

    // 4 float4 per thread, fully unrolled -> front-batched loads, high MLP.
    float4 acc[4];
    #pragma unroll
    for (int u = 0; u < 4; ++u) {
        acc[u].x = 0.f; acc[u].y = 0.f; acc[u].z = 0.f; acc[u].w = 0.f;
    }

    if (c0 != 0.f) {
        #pragma unroll
        for (int u = 0; u < 4; ++u) {
            float4 v = __ldg(&h1[tid + u * 256]);
            acc[u].x = fmaf(c0, v.x, acc[u].x);
            acc[u].y = fmaf(c0, v.y, acc[u].y);
            acc[u].z = fmaf(c0, v.z, acc[u].z);
            acc[u].w = fmaf(c0, v.w, acc[u].w);
        }
    }
    if (c1 != 0.f) {
        #pragma unroll
        for (int u = 0; u < 4; ++u) {
            float4 v = __ldg(&h2[tid + u * 256]);
            acc[u].x = fmaf(c1, v.x, acc[u].x);
            acc[u].y = fmaf(c1, v.y, acc[u].y);
            acc[u].z = fmaf(c1, v.z, acc[u].z);
            acc[u].w = fmaf(c1, v.w, acc[u].w);
        }
    }
    if (c2 != 0.f) {
        #pragma unroll
        for (int u = 0; u < 4; ++u) {
            float4 v = __ldg(&r1[tid + u * 256]);
            acc[u].x = fmaf(c2, v.x, acc[u].x);
            acc[u].y = fmaf(c2, v.y, acc[u].y);
            acc[u].z = fmaf(c2, v.z, acc[u].z);
            acc[u].w = fmaf(c2, v.w, acc[u].w);
        }
    }
    if (c3 != 0.f) {
        #pragma unroll
        for (int u = 0; u < 4; ++u) {
            float4 v = __ldg(&r2[tid + u * 256]);
            acc[u].x = fmaf(c3, v.x, acc[u].x);
            acc[u].y = fmaf(c3, v.y, acc[u].y);
            acc[u].z = fmaf(c3, v.z, acc[u].z);
            acc[u].w = fmaf(c3, v.w, acc[u].w);
        }
    }

    #pragma unroll
    for (int u = 0; u < 4; ++u) {
        float4 r;
        r.x = fminf(fmaxf(acc[u].x, 0.f), 1.f);
        r.y = fminf(fmaxf(acc[u].y, 0.f), 1.f);
        r.z = fminf(fmaxf(acc[u].z, 0.f), 1.f);
        r.w = fminf(fmaxf(acc[u].w, 0.f), 1.f);
        o[tid + u * 256] = r;
    }
}

extern "C" void kernel_launch(void* const* d_in, const int* in_sizes, int n_in,
                              void* d_out, int out_size)
{
    const int*   pid    = (const int*)  d_in[0];   // program_id  (128*64)
    const float* hearts = (const float*)d_in[1];   // (128,64,2,64,64)
    const float* rects  = (const float*)d_in[2];   // (128,64,2,64,64)
    float*       out    = (float*)d_out;           // (128,64,64,64)

    const int pairs = in_sizes[0];                 // 8192
    tgm_kernel<<<pairs, 256>>>(pid, hearts, rects, out);
}

// round 7
// speedup vs baseline: 1.0346x; 1.0346x over previous
#include <cuda_runtime.h>
#include <cstdint>

// Branch-free 2-source encoding of the COEFFS table.
// Every program row has at most 2 nonzero coefficients.
// src selector: 0=h1, 1=h2, 2=r1, 3=r2. One-plane programs duplicate
// the source with coeff 0 (second load is an L1 hit -> no DRAM cost).
//
//  p : coeffs          -> (selA, cA, selB, cB)
//  0 : [ 1, 0, 0, 0]   -> (0, +1, 0,  0)
//  1 : [ 0, 0, 1, 0]   -> (2, +1, 2,  0)
//  2 : [ 1, 0, 1, 0]   -> (0, +1, 2, +1)
//  3 : [ 1, 1, 0, 0]   -> (0, +1, 1, +1)
//  4 : [ 0, 0, 1, 1]   -> (2, +1, 3, +1)
//  5 : [ 1,-1, 0, 0]   -> (0, +1, 1, -1)
//  6 : [ 1, 0,-1, 0]   -> (0, +1, 2, -1)
//  7 : [-1, 0, 1, 0]   -> (0, -1, 2, +1)
//  8 : [ 0, 0, 1,-1]   -> (2, +1, 3, -1)

__constant__ int PSEL[9][2] = {
    {0,0},{2,2},{0,2},{0,1},{2,3},{0,1},{0,2},{0,2},{2,3}
};
__constant__ float PC[9][2] = {
    { 1.f, 0.f},   // p0
    { 1.f, 0.f},   // p1
    { 1.f, 1.f},   // p2
    { 1.f, 1.f},   // p3
    { 1.f, 1.f},   // p4
    { 1.f,-1.f},   // p5
    { 1.f,-1.f},   // p6
    {-1.f, 1.f},   // p7
    { 1.f,-1.f}    // p8  (was the R6 bug: must be -1, not +1)
};

// One block per (b,s) pair: 4096 f32 out, two 4096-f32 source planes.
// 256 threads x 4 float4 each. All 8 loads are independent and
// front-batched (no branches in the body) -> per-thread MLP = 8.

__global__ __launch_bounds__(256, 5)
void tgm_kernel(const int* __restrict__ pid,
                const float* __restrict__ hearts,
                const float* __restrict__ rects,
                float* __restrict__ out)
{
    const int pair = blockIdx.x;              // 0..8191
    const int p    = __ldg(pid + pair);       // 0..8

    const int   sA = PSEL[p][0];
    const int   sB = PSEL[p][1];
    const float cA = PC[p][0];
    const float cB = PC[p][1];

    const size_t in_base = (size_t)pair * 8192;   // 2 planes per tensor

    const float* baseA = (sA < 2 ? hearts : rects) + in_base + (size_t)(sA & 1) * 4096;
    const float* baseB = (sB < 2 ? hearts : rects) + in_base + (size_t)(sB & 1) * 4096;

    const float4* A = (const float4*)baseA;
    const float4* B = (const float4*)baseB;
    float4*       O = (float4*)(out + (size_t)pair * 4096);

    const int t = threadIdx.x;

    // Front-batch all 8 loads (evict-first: single-use streaming data).
    float4 va[4], vb[4];
    #pragma unroll
    for (int u = 0; u < 4; ++u) va[u] = __ldcs(&A[t + u * 256]);
    #pragma unroll
    for (int u = 0; u < 4; ++u) vb[u] = __ldcs(&B[t + u * 256]);

    #pragma unroll
    for (int u = 0; u < 4; ++u) {
        float4 r;
        r.x = fmaf(cB, vb[u].x, cA * va[u].x);
        r.y = fmaf(cB, vb[u].y, cA * va[u].y);
        r.z = fmaf(cB, vb[u].z, cA * va[u].z);
        r.w = fmaf(cB, vb[u].w, cA * va[u].w);
        r.x = fminf(fmaxf(r.x, 0.f), 1.f);
        r.y = fminf(fmaxf(r.y, 0.f), 1.f);
        r.z = fminf(fmaxf(r.z, 0.f), 1.f);
        r.w = fminf(fmaxf(r.w, 0.f), 1.f);
        __stcs(&O[t + u * 256], r);
    }
}

extern "C" void kernel_launch(void* const* d_in, const int* in_sizes, int n_in,
                              void* d_out, int out_size)
{
    const int*   pid    = (const int*)  d_in[0];   // program_id  (128*64)
    const float* hearts = (const float*)d_in[1];   // (128,64,2,64,64)
    const float* rects  = (const float*)d_in[2];   // (128,64,2,64,64)
    float*       out    = (float*)d_out;           // (128,64,64,64)

    const int pairs = in_sizes[0];                 // 8192
    tgm_kernel<<<pairs, 256>>>(pid, hearts, rects, out);
}